// round 11
// baseline (speedup 1.0000x reference)
#include <cuda_runtime.h>

#define BLOCK 128
#define OUTB  256                     // 2 outputs/thread -> grid 1024
#define HALO_L 10
#define TILE  272                     // need idx 0..268

typedef unsigned long long u64;

static __device__ __forceinline__ u64 pk2(float a, float b) {
    u64 v; asm("mov.b64 %0,{%1,%2};" : "=l"(v) : "f"(a), "f"(b)); return v;
}
static __device__ __forceinline__ void up2(u64 v, float& a, float& b) {
    asm("mov.b64 {%0,%1},%2;" : "=f"(a), "=f"(b) : "l"(v));
}
static __device__ __forceinline__ u64 fma2(u64 a, u64 b, u64 c) {
    u64 d; asm("fma.rn.f32x2 %0,%1,%2,%3;" : "=l"(d) : "l"(a), "l"(b), "l"(c)); return d;
}
static __device__ __forceinline__ u64 add2(u64 a, u64 b) {
    u64 d; asm("add.rn.f32x2 %0,%1,%2;" : "=l"(d) : "l"(a), "l"(b)); return d;
}
static __device__ __forceinline__ float fsqrt_ap(float x) {
    float r; asm("sqrt.approx.f32 %0,%1;" : "=f"(r) : "f"(x)); return r;
}

// Fully fused single kernel. Per block, build the merged coefficient table in
// shared memory with fully batched (predicated) loads, then evaluate.
//   Q[l][e3][k], e3 = e+3, e in [-3,3]:
//     e=0  : a[k,l] + b[k,l,0] + c[k,l,0]
//     e=-m : b[k,l,m]   (envelope at n-l-m)
//     e=+m : c[k,l,m]   (envelope at n-l+m)
//   y[n] = sum_l x[n-l] * sum_e3 Horner_{k=7..0}(Q[l,e3,:], r[n-l+e3-3])
__global__ __launch_bounds__(BLOCK)
void gmp_kernel(const float2* __restrict__ x,
                const float* __restrict__ ar, const float* __restrict__ ai,
                const float* __restrict__ br, const float* __restrict__ bi,
                const float* __restrict__ cr, const float* __restrict__ ci,
                float2* __restrict__ y, int N) {
    __shared__ float2 sx[TILE];
    __shared__ u64 srr[TILE];
    __shared__ __align__(16) u64 sQ[448];   // (l*7+e3)*8 + k

    const int t = threadIdx.x;
    const int base = blockIdx.x * OUTB;

    // ---- phase 1: issue ALL global loads (high MLP, one latency round) ----
    // 4 table entries per thread, predicated loads (no branchy serialization)
    float tre[4], tim[4];
    int tdst[4];
    #pragma unroll
    for (int q = 0; q < 4; q++) {
        const int i  = t + q * BLOCK;        // 0..511, only <448 valid
        const int k  = i & 7;
        const int e3 = (i >> 3) % 7;
        const int l  = i / 56;
        const int kl = k * 8 + l;            // a[k][l], row-major (8,8)
        float re = 0.f, im = 0.f;
        if (i < 448) {
            if (e3 <= 3) { int m = 3 - e3; re += br[kl * 4 + m]; im += bi[kl * 4 + m]; }
            if (e3 >= 3) { int m = e3 - 3; re += cr[kl * 4 + m]; im += ci[kl * 4 + m]; }
            if (e3 == 3) { re += ar[kl];  im += ai[kl]; }
        }
        tre[q] = re; tim[q] = im;
        tdst[q] = (l * 7 + e3) * 8 + k;
    }
    // 3 tile samples per thread, index-clamped (== reference's jnp.clip)
    float2 tv[3];
    #pragma unroll
    for (int q = 0; q < 3; q++) {
        const int i = t + q * BLOCK;
        int g = base - HALO_L + i;
        g = min(max(g, 0), N - 1);
        if (i < 269) tv[q] = x[g];
    }

    // ---- phase 2: stores to shared ----
    #pragma unroll
    for (int q = 0; q < 4; q++) {
        const int i = t + q * BLOCK;
        if (i < 448) sQ[tdst[q]] = pk2(tre[q], tim[q]);
    }
    #pragma unroll
    for (int q = 0; q < 3; q++) {
        const int i = t + q * BLOCK;
        if (i < 269) {
            float2 v = tv[q];
            sx[i] = v;
            float r = fsqrt_ap(fmaf(v.x, v.x, v.y * v.y));
            srr[i] = pk2(r, r);
        }
    }
    __syncthreads();

    // rr[i] <-> envelope |x| at n0-10+i, n0 = base + 2t (register-resident)
    u64 rr[15];
    #pragma unroll
    for (int i = 0; i < 15; i++) rr[i] = srr[2 * t + i];

    float yr0 = 0.f, yi0 = 0.f, yr1 = 0.f, yi1 = 0.f;

    #pragma unroll
    for (int l = 0; l < 8; l++) {
        u64 w0 = 0ULL, w1 = 0ULL;
        #pragma unroll
        for (int e3 = 0; e3 < 7; e3++) {
            const ulonglong2* C = (const ulonglong2*)&sQ[(l * 7 + e3) * 8];
            ulonglong2 c01 = C[0], c23 = C[1], c45 = C[2], c67 = C[3];   // LDS.128 imm
            const int idx = 7 - l + e3;           // compile-time rr index 0..13
            u64 r0 = rr[idx];
            u64 r1 = rr[idx + 1];
            u64 h0 = fma2(c67.y, r0, c67.x);      // c7*r + c6
            u64 h1 = fma2(c67.y, r1, c67.x);
            h0 = fma2(h0, r0, c45.y);  h1 = fma2(h1, r1, c45.y);
            h0 = fma2(h0, r0, c45.x);  h1 = fma2(h1, r1, c45.x);
            h0 = fma2(h0, r0, c23.y);  h1 = fma2(h1, r1, c23.y);
            h0 = fma2(h0, r0, c23.x);  h1 = fma2(h1, r1, c23.x);
            h0 = fma2(h0, r0, c01.y);  h1 = fma2(h1, r1, c01.y);
            h0 = fma2(h0, r0, c01.x);  h1 = fma2(h1, r1, c01.x);   // k=0
            w0 = add2(w0, h0);
            w1 = add2(w1, h1);
        }
        float2 xl0 = sx[2 * t + 10 - l];          // carrier x[n0-l]
        float2 xl1 = sx[2 * t + 11 - l];          // carrier x[n0+1-l]
        float wr0, wi0, wr1, wi1;
        up2(w0, wr0, wi0);
        up2(w1, wr1, wi1);
        yr0 = fmaf(xl0.x, wr0, fmaf(-xl0.y, wi0, yr0));
        yi0 = fmaf(xl0.x, wi0, fmaf( xl0.y, wr0, yi0));
        yr1 = fmaf(xl1.x, wr1, fmaf(-xl1.y, wi1, yr1));
        yi1 = fmaf(xl1.x, wi1, fmaf( xl1.y, wr1, yi1));
    }

    int n0 = base + 2 * t;
    if (n0 + 1 < N) {
        ((float4*)y)[n0 >> 1] = make_float4(yr0, yi0, yr1, yi1);
    } else if (n0 < N) {
        y[n0] = make_float2(yr0, yi0);
    }
}

extern "C" void kernel_launch(void* const* d_in, const int* in_sizes, int n_in,
                              void* d_out, int out_size) {
    const float2* x  = (const float2*)d_in[0];
    const float*  ar = (const float*)d_in[1];
    const float*  ai = (const float*)d_in[2];
    const float*  br = (const float*)d_in[3];
    const float*  bi = (const float*)d_in[4];
    const float*  cr = (const float*)d_in[5];
    const float*  ci = (const float*)d_in[6];
    float2* y = (float2*)d_out;
    int N = in_sizes[0] / 2;

    int grid = (N + OUTB - 1) / OUTB;
    gmp_kernel<<<grid, BLOCK>>>(x, ar, ai, br, bi, cr, ci, y, N);
}